// round 3
// baseline (speedup 1.0000x reference)
#include <cuda_runtime.h>
#include <math.h>

#define BROWS 4096
#define DIN   2048
#define DHID  3584
#define DOUT  2048

// ---------------- scratch (static __device__, no allocation) ----------------
__device__ float g_scale[BROWS];                         // 16 KB
__device__ float g_xexp[(size_t)BROWS * DHID];           // 56 MB
__device__ float g_wff [(size_t)DOUT * DHID];            // 28 MB (flipped W_female)
__device__ float g_male[(size_t)BROWS * DOUT];           // 32 MB
__device__ float g_fem [(size_t)BROWS * DOUT];           // 32 MB

// ---------------- utility: block reduce-sum + broadcast ----------------
__device__ __forceinline__ float blockReduceSum(float v) {
    __shared__ float sh[33];
    int lane = threadIdx.x & 31, wid = threadIdx.x >> 5;
    #pragma unroll
    for (int o = 16; o; o >>= 1) v += __shfl_down_sync(0xffffffffu, v, o);
    if (lane == 0) sh[wid] = v;
    __syncthreads();
    if (wid == 0) {
        v = (threadIdx.x < (blockDim.x >> 5)) ? sh[lane] : 0.f;
        #pragma unroll
        for (int o = 16; o; o >>= 1) v += __shfl_down_sync(0xffffffffu, v, o);
        if (lane == 0) sh[32] = v;
    }
    __syncthreads();
    return sh[32];
}

// ---------------- 1) Vesica row-scale ----------------
__global__ void __launch_bounds__(256) k_scale(const float* __restrict__ x) {
    int b  = blockIdx.x;
    int bp = (b == 0) ? (BROWS - 1) : (b - 1);
    const float4* r0 = (const float4*)(x + (size_t)b  * DIN);
    const float4* r1 = (const float4*)(x + (size_t)bp * DIN);
    float ss = 0.f;
    for (int i = threadIdx.x; i < DIN / 4; i += 256) {
        float4 a = r0[i], c = r1[i];
        float dx = a.x - c.x, dy = a.y - c.y, dz = a.z - c.z, dw = a.w - c.w;
        ss += dx*dx + dy*dy + dz*dz + dw*dw;
    }
    ss = blockReduceSum(ss);
    if (threadIdx.x == 0) {
        float dist = sqrtf(ss);
        float ov = fmaxf(0.f, 1.f - fabsf(dist - 1.f));
        g_scale[b] = 1.f + ov;
    }
}

// ---------------- 2) flip W_female along hidden dim ----------------
__global__ void __launch_bounds__(256) k_flip(const float* __restrict__ wf) {
    size_t i = (size_t)blockIdx.x * 256 + threadIdx.x;
    if (i < (size_t)DOUT * DHID) {
        int o = (int)(i / DHID);
        int h = (int)(i % DHID);
        g_wff[i] = wf[(size_t)o * DHID + (DHID - 1 - h)];
    }
}

// ---------------- 3) NT SGEMM: C[M,N] = (A * rowScale) @ Bm^T ----------------
// A: [M,K] row-major, Bm: [N,K] row-major. BM=BN=128, BK=8, 256 thr, 8x8/thr.
// EPI=1: phase-shift epilogue (cols where n%512 < 2).
template<int EPI>
__global__ void __launch_bounds__(256)
sgemm_nt(const float* __restrict__ A, const float* __restrict__ Bm,
         float* __restrict__ C, int M, int N, int K,
         const float* __restrict__ rowScale)
{
    constexpr int BM = 128, BN = 128, BK = 8;
    __shared__ float As[BK][BM + 4];
    __shared__ float Bs[BK][BN + 4];

    const int t  = threadIdx.x;
    const int tx = t & 15;          // 0..15 -> N direction
    const int ty = t >> 4;          // 0..15 -> M direction
    const int rowBlock = blockIdx.y * BM;
    const int colBlock = blockIdx.x * BN;

    const int lrow  = t >> 1;       // 0..127: staging row
    const int lcol4 = (t & 1) * 4;  // 0 or 4: staging k-offset

    const float ascale = rowScale ? rowScale[rowBlock + lrow] : 1.f;
    const float* Aptr = A  + (size_t)(rowBlock + lrow) * K + lcol4;
    const float* Bptr = Bm + (size_t)(colBlock + lrow) * K + lcol4;

    float acc[8][8];
    #pragma unroll
    for (int i = 0; i < 8; i++)
        #pragma unroll
        for (int j = 0; j < 8; j++) acc[i][j] = 0.f;

    for (int kt = 0; kt < K; kt += BK) {
        float4 av = *(const float4*)(Aptr + kt);
        float4 bv = *(const float4*)(Bptr + kt);
        av.x *= ascale; av.y *= ascale; av.z *= ascale; av.w *= ascale;
        As[lcol4 + 0][lrow] = av.x; As[lcol4 + 1][lrow] = av.y;
        As[lcol4 + 2][lrow] = av.z; As[lcol4 + 3][lrow] = av.w;
        Bs[lcol4 + 0][lrow] = bv.x; Bs[lcol4 + 1][lrow] = bv.y;
        Bs[lcol4 + 2][lrow] = bv.z; Bs[lcol4 + 3][lrow] = bv.w;
        __syncthreads();

        #pragma unroll
        for (int k = 0; k < BK; k++) {
            float4 ra0 = *(const float4*)&As[k][ty * 8];
            float4 ra1 = *(const float4*)&As[k][ty * 8 + 4];
            float4 rb0 = *(const float4*)&Bs[k][tx * 8];
            float4 rb1 = *(const float4*)&Bs[k][tx * 8 + 4];
            float ra[8] = {ra0.x, ra0.y, ra0.z, ra0.w, ra1.x, ra1.y, ra1.z, ra1.w};
            float rb[8] = {rb0.x, rb0.y, rb0.z, rb0.w, rb1.x, rb1.y, rb1.z, rb1.w};
            #pragma unroll
            for (int i = 0; i < 8; i++)
                #pragma unroll
                for (int j = 0; j < 8; j++)
                    acc[i][j] = fmaf(ra[i], rb[j], acc[i][j]);
        }
        __syncthreads();
    }

    // epilogue
    #pragma unroll
    for (int i = 0; i < 8; i++) {
        int r = rowBlock + ty * 8 + i;
        float* crow = C + (size_t)r * N + colBlock + tx * 8;
        float v[8];
        #pragma unroll
        for (int j = 0; j < 8; j++) {
            float val = acc[i][j];
            if (EPI) {
                int c = colBlock + tx * 8 + j;
                int o = c & 511;
                if (o < 2) {
                    int ci = c >> 9;   // circle index 0..6
                    float ph = 6.28318530717958647692f * (float)ci / 7.0f;
                    val *= (o == 0) ? cosf(ph) : sinf(ph);
                }
            }
            v[j] = val;
        }
        *(float4*)(crow)     = make_float4(v[0], v[1], v[2], v[3]);
        *(float4*)(crow + 4) = make_float4(v[4], v[5], v[6], v[7]);
    }
}

// ---------------- 4) phase-lock blend ----------------
__global__ void __launch_bounds__(256) k_final(float* __restrict__ out) {
    int b = blockIdx.x;
    const float4* mr = (const float4*)(g_male + (size_t)b * DOUT);
    const float4* fr = (const float4*)(g_fem  + (size_t)b * DOUT);
    int i0 = threadIdx.x, i1 = threadIdx.x + 256;   // 512 float4 per row
    float4 m0 = mr[i0], m1 = mr[i1];
    float4 f0 = fr[i0], f1 = fr[i1];
    float s = m0.x*f0.x + m0.y*f0.y + m0.z*f0.z + m0.w*f0.w
            + m1.x*f1.x + m1.y*f1.y + m1.z*f1.z + m1.w*f1.w;
    s = blockReduceSum(s);
    float pl = 1.f / (1.f + expf(-s));
    float om = 1.f - pl;
    float4* o4 = (float4*)(out + (size_t)b * DOUT);
    o4[i0] = make_float4(pl*m0.x + om*f0.x, pl*m0.y + om*f0.y,
                         pl*m0.z + om*f0.z, pl*m0.w + om*f0.w);
    o4[i1] = make_float4(pl*m1.x + om*f1.x, pl*m1.y + om*f1.y,
                         pl*m1.z + om*f1.z, pl*m1.w + om*f1.w);
}

// ---------------- launch ----------------
extern "C" void kernel_launch(void* const* d_in, const int* in_sizes, int n_in,
                              void* d_out, int out_size) {
    const float* x   = (const float*)d_in[0];   // [4096, 2048]
    const float* wfl = (const float*)d_in[1];   // [7, 512, 2048] == [3584, 2048]
    const float* wm  = (const float*)d_in[2];   // [2048, 3584]
    const float* wfe = (const float*)d_in[3];   // [2048, 3584]
    float* out = (float*)d_out;

    float* xexp; cudaGetSymbolAddress((void**)&xexp, g_xexp);
    float* wff;  cudaGetSymbolAddress((void**)&wff,  g_wff);
    float* male; cudaGetSymbolAddress((void**)&male, g_male);
    float* fem;  cudaGetSymbolAddress((void**)&fem,  g_fem);
    float* scal; cudaGetSymbolAddress((void**)&scal, g_scale);

    // 1) row scales
    k_scale<<<BROWS, 256>>>(x);

    // 2) flip W_female (independent of 1; same stream keeps ordering trivial)
    {
        size_t tot = (size_t)DOUT * DHID;
        k_flip<<<(unsigned)((tot + 255) / 256), 256>>>(wfe);
    }

    // 3) GEMM1: x_expanded = (x*scale) @ W_flower^T, phase epilogue
    {
        dim3 grid(DHID / 128, BROWS / 128);
        sgemm_nt<1><<<grid, 256>>>(x, wfl, xexp, BROWS, DHID, DIN, scal);
    }

    // 4) GEMM2a/2b: male / female
    {
        dim3 grid(DOUT / 128, BROWS / 128);
        sgemm_nt<0><<<grid, 256>>>(xexp, wm,  male, BROWS, DOUT, DHID, nullptr);
        sgemm_nt<0><<<grid, 256>>>(xexp, wff, fem,  BROWS, DOUT, DHID, nullptr);
    }

    // 5) blend
    k_final<<<BROWS, 256>>>(out);
}

// round 5
// speedup vs baseline: 2.5378x; 2.5378x over previous
#include <cuda_runtime.h>
#include <cuda_fp16.h>
#include <cstdint>
#include <math.h>

#define BROWS 4096
#define DIN   2048
#define DHID  3584
#define DOUT  2048

// ---------------- scratch (static __device__, no allocation) ----------------
__device__ float  g_scale[BROWS];
__device__ __align__(16) __half g_xh  [(size_t)BROWS*DIN];
__device__ __align__(16) __half g_xl  [(size_t)BROWS*DIN];
__device__ __align__(16) __half g_wflh[(size_t)DHID*DIN];
__device__ __align__(16) __half g_wfll[(size_t)DHID*DIN];
__device__ __align__(16) __half g_wmh [(size_t)DOUT*DHID];
__device__ __align__(16) __half g_wml [(size_t)DOUT*DHID];
__device__ __align__(16) __half g_wfh [(size_t)DOUT*DHID];   // flipped female hi
__device__ __align__(16) __half g_wfl2[(size_t)DOUT*DHID];   // flipped female lo
__device__ __align__(16) __half g_xeh [(size_t)BROWS*DHID];
__device__ __align__(16) __half g_xel [(size_t)BROWS*DHID];
__device__ __align__(16) float  g_male[(size_t)BROWS*DOUT];
__device__ __align__(16) float  g_fem [(size_t)BROWS*DOUT];

// ---------------- PTX helpers (all generic sm_80-era, legal on compute_103) ----
__device__ __forceinline__ uint32_t smem_u32(const void* p) {
    uint32_t a;
    asm("{ .reg .u64 t; cvta.to.shared.u64 t, %1; cvt.u32.u64 %0, t; }" : "=r"(a) : "l"(p));
    return a;
}
#define CP16(dst, src) asm volatile("cp.async.cg.shared.global [%0], [%1], 16;" :: "r"(dst), "l"(src))
#define CP_COMMIT()    asm volatile("cp.async.commit_group;" ::: "memory")
#define CP_WAIT1()     asm volatile("cp.async.wait_group 1;" ::: "memory")
#define CP_WAIT0()     asm volatile("cp.async.wait_group 0;" ::: "memory")

__device__ __forceinline__ void ldsm4(uint32_t* r, uint32_t addr) {
    asm volatile("ldmatrix.sync.aligned.m8n8.x4.shared.b16 {%0,%1,%2,%3}, [%4];"
                 : "=r"(r[0]), "=r"(r[1]), "=r"(r[2]), "=r"(r[3]) : "r"(addr));
}
__device__ __forceinline__ void ldsm2(uint32_t* r, uint32_t addr) {
    asm volatile("ldmatrix.sync.aligned.m8n8.x2.shared.b16 {%0,%1}, [%2];"
                 : "=r"(r[0]), "=r"(r[1]) : "r"(addr));
}
__device__ __forceinline__ void mma16816(float* c, const uint32_t* a, const uint32_t* b) {
    asm volatile(
        "mma.sync.aligned.m16n8k16.row.col.f32.f16.f16.f32 "
        "{%0,%1,%2,%3}, {%4,%5,%6,%7}, {%8,%9}, {%0,%1,%2,%3};"
        : "+f"(c[0]), "+f"(c[1]), "+f"(c[2]), "+f"(c[3])
        : "r"(a[0]), "r"(a[1]), "r"(a[2]), "r"(a[3]), "r"(b[0]), "r"(b[1]));
}

// ---------------- GEMM config ----------------
#define GBM 128
#define GBN 64
#define GBK 32
#define LDS_ROW 40                       // 32 + 8 halfs padding (80B row stride)
#define OFF_AH 0
#define OFF_AL (GBM * LDS_ROW * 2)       // 10240
#define OFF_BH (2 * GBM * LDS_ROW * 2)   // 20480
#define OFF_BL (OFF_BH + GBN * LDS_ROW * 2)
#define STAGE  (OFF_BL + GBN * LDS_ROW * 2)   // 30720 B
#define GSMEM  (2 * STAGE)
#define INV2048 4.8828125e-4f

__device__ __forceinline__ void cp_stage(
    uint32_t base, const __half* __restrict__ Ah, const __half* __restrict__ Al,
    const __half* __restrict__ Bh, const __half* __restrict__ Bl,
    int rowBlock, int colBlock, int K, int kt, int t)
{
    #pragma unroll
    for (int i = 0; i < 2; i++) {                 // A: 512 chunks of 16B
        int c = t + i * 256;
        int r = c >> 2, kc = (c & 3) * 8;
        uint32_t doff = (uint32_t)((r * LDS_ROW + kc) * 2);
        size_t g = (size_t)(rowBlock + r) * K + kt + kc;
        CP16(base + OFF_AH + doff, Ah + g);
        CP16(base + OFF_AL + doff, Al + g);
    }
    {                                             // B: 256 chunks
        int r = t >> 2, kc = (t & 3) * 8;
        uint32_t doff = (uint32_t)((r * LDS_ROW + kc) * 2);
        size_t g = (size_t)(colBlock + r) * K + kt + kc;
        CP16(base + OFF_BH + doff, Bh + g);
        CP16(base + OFF_BL + doff, Bl + g);
    }
}

// C = (Ah + Al/2048) @ (Bh + Bl/2048)^T, al*bl dropped.
// EPI=1: phase-shift epilogue, split-write half C0(hi)/C1(lo*2048).
// EPI=0: z selects weights/outputs; float write.
template<int EPI>
__global__ void __launch_bounds__(256, 2)
gemm_fp16x3(const __half* __restrict__ Ah, const __half* __restrict__ Al,
            const __half* __restrict__ Bh0, const __half* __restrict__ Bl0,
            const __half* __restrict__ Bh1, const __half* __restrict__ Bl1,
            void* __restrict__ C0v, void* __restrict__ C1v,
            int K, int N)
{
    extern __shared__ char smem_raw[];
    const uint32_t sb = smem_u32(smem_raw);
    const int t = threadIdx.x, lane = t & 31, wid = t >> 5;
    const int wm = wid & 3, wn = wid >> 2;     // 4 x 2 warps, 32x32 tiles
    const int rowBlock = blockIdx.y * GBM;
    const int colBlock = blockIdx.x * GBN;

    const __half* Bh = (EPI == 1 || blockIdx.z == 0) ? Bh0 : Bh1;
    const __half* Bl = (EPI == 1 || blockIdx.z == 0) ? Bl0 : Bl1;

    float acc_hh[2][4][4];
    float acc_x [2][4][4];
    #pragma unroll
    for (int mi = 0; mi < 2; mi++)
        #pragma unroll
        for (int ni = 0; ni < 4; ni++)
            #pragma unroll
            for (int e = 0; e < 4; e++) { acc_hh[mi][ni][e] = 0.f; acc_x[mi][ni][e] = 0.f; }

    const int NK = K / GBK;
    cp_stage(sb, Ah, Al, Bh, Bl, rowBlock, colBlock, K, 0, t);
    CP_COMMIT();

    // precomputed ldmatrix lane offsets
    const int a_row = (lane & 15), a_col = ((lane >> 4) << 3);
    const int b_row = (lane & 7),  b_col = (((lane >> 3) & 1) << 3);

    for (int it = 0; it < NK; it++) {
        if (it + 1 < NK) {
            cp_stage(sb + ((it + 1) & 1) * STAGE, Ah, Al, Bh, Bl,
                     rowBlock, colBlock, K, (it + 1) * GBK, t);
            CP_COMMIT();
            CP_WAIT1();
        } else {
            CP_WAIT0();
        }
        __syncthreads();

        const uint32_t base = sb + (it & 1) * STAGE;
        #pragma unroll
        for (int kk = 0; kk < GBK; kk += 16) {
            uint32_t a_h[2][4], a_l[2][4];
            #pragma unroll
            for (int mi = 0; mi < 2; mi++) {
                int row = wm * 32 + mi * 16 + a_row;
                uint32_t off = (uint32_t)((row * LDS_ROW + kk + a_col) * 2);
                ldsm4(a_h[mi], base + OFF_AH + off);
                ldsm4(a_l[mi], base + OFF_AL + off);
            }
            uint32_t b_h[4][2], b_l[4][2];
            #pragma unroll
            for (int ni = 0; ni < 4; ni++) {
                int row = wn * 32 + ni * 8 + b_row;
                uint32_t off = (uint32_t)((row * LDS_ROW + kk + b_col) * 2);
                ldsm2(b_h[ni], base + OFF_BH + off);
                ldsm2(b_l[ni], base + OFF_BL + off);
            }
            #pragma unroll
            for (int mi = 0; mi < 2; mi++)
                #pragma unroll
                for (int ni = 0; ni < 4; ni++) {
                    mma16816(acc_hh[mi][ni], a_h[mi], b_h[ni]);
                    mma16816(acc_x [mi][ni], a_h[mi], b_l[ni]);
                    mma16816(acc_x [mi][ni], a_l[mi], b_h[ni]);
                }
        }
        __syncthreads();
    }

    // ---------------- epilogue ----------------
    #pragma unroll
    for (int mi = 0; mi < 2; mi++) {
        #pragma unroll
        for (int ni = 0; ni < 4; ni++) {
            float v0 = acc_hh[mi][ni][0] + acc_x[mi][ni][0] * INV2048;
            float v1 = acc_hh[mi][ni][1] + acc_x[mi][ni][1] * INV2048;
            float v2 = acc_hh[mi][ni][2] + acc_x[mi][ni][2] * INV2048;
            float v3 = acc_hh[mi][ni][3] + acc_x[mi][ni][3] * INV2048;
            int r0 = rowBlock + wm * 32 + mi * 16 + (lane >> 2);
            int r1 = r0 + 8;
            int c  = colBlock + wn * 32 + ni * 8 + (lane & 3) * 2;
            if (EPI == 1) {
                int o = c & 511;
                if (o == 0) {
                    int ci = c >> 9;
                    float ph = 6.28318530717958647692f * (float)ci / 7.0f;
                    float p0 = cosf(ph), p1 = sinf(ph);
                    v0 *= p0; v1 *= p1; v2 *= p0; v3 *= p1;
                }
                __half* Ch = (__half*)C0v;
                __half* Cl = (__half*)C1v;
                __half h0 = __float2half_rn(v0), h1 = __float2half_rn(v1);
                __half h2 = __float2half_rn(v2), h3 = __float2half_rn(v3);
                __half l0 = __float2half_rn((v0 - __half2float(h0)) * 2048.f);
                __half l1 = __float2half_rn((v1 - __half2float(h1)) * 2048.f);
                __half l2 = __float2half_rn((v2 - __half2float(h2)) * 2048.f);
                __half l3 = __float2half_rn((v3 - __half2float(h3)) * 2048.f);
                *(__half2*)(Ch + (size_t)r0 * N + c) = __halves2half2(h0, h1);
                *(__half2*)(Ch + (size_t)r1 * N + c) = __halves2half2(h2, h3);
                *(__half2*)(Cl + (size_t)r0 * N + c) = __halves2half2(l0, l1);
                *(__half2*)(Cl + (size_t)r1 * N + c) = __halves2half2(l2, l3);
            } else {
                float* Cf = (blockIdx.z == 0) ? (float*)C0v : (float*)C1v;
                *(float2*)(Cf + (size_t)r0 * N + c) = make_float2(v0, v1);
                *(float2*)(Cf + (size_t)r1 * N + c) = make_float2(v2, v3);
            }
        }
    }
}

// ---------------- elementwise kernels ----------------
__device__ __forceinline__ float blockReduceSum(float v) {
    __shared__ float sh[33];
    int lane = threadIdx.x & 31, wid = threadIdx.x >> 5;
    #pragma unroll
    for (int o = 16; o; o >>= 1) v += __shfl_down_sync(0xffffffffu, v, o);
    if (lane == 0) sh[wid] = v;
    __syncthreads();
    if (wid == 0) {
        v = (threadIdx.x < (blockDim.x >> 5)) ? sh[lane] : 0.f;
        #pragma unroll
        for (int o = 16; o; o >>= 1) v += __shfl_down_sync(0xffffffffu, v, o);
        if (lane == 0) sh[32] = v;
    }
    __syncthreads();
    return sh[32];
}

__global__ void __launch_bounds__(256) k_scale(const float* __restrict__ x) {
    int b  = blockIdx.x;
    int bp = (b == 0) ? (BROWS - 1) : (b - 1);
    const float4* r0 = (const float4*)(x + (size_t)b  * DIN);
    const float4* r1 = (const float4*)(x + (size_t)bp * DIN);
    float ss = 0.f;
    for (int i = threadIdx.x; i < DIN / 4; i += 256) {
        float4 a = r0[i], c = r1[i];
        float dx = a.x - c.x, dy = a.y - c.y, dz = a.z - c.z, dw = a.w - c.w;
        ss += dx*dx + dy*dy + dz*dz + dw*dw;
    }
    ss = blockReduceSum(ss);
    if (threadIdx.x == 0) {
        float dist = sqrtf(ss);
        g_scale[b] = 1.f + fmaxf(0.f, 1.f - fabsf(dist - 1.f));
    }
}

__device__ __forceinline__ void split_store(__half* hi, __half* lo, size_t idx2, float a, float b) {
    __half ha = __float2half_rn(a), hb = __float2half_rn(b);
    __half la = __float2half_rn((a - __half2float(ha)) * 2048.f);
    __half lb = __float2half_rn((b - __half2float(hb)) * 2048.f);
    ((__half2*)hi)[idx2] = __halves2half2(ha, hb);
    ((__half2*)lo)[idx2] = __halves2half2(la, lb);
}

__global__ void __launch_bounds__(256) k_split_x(const float* __restrict__ x) {
    size_t i = (size_t)blockIdx.x * 256 + threadIdx.x;
    if (i >= (size_t)BROWS * DIN / 4) return;
    int row = (int)(i / (DIN / 4));
    float s = g_scale[row];
    float4 v = ((const float4*)x)[i];
    split_store(g_xh, g_xl, i * 2 + 0, v.x * s, v.y * s);
    split_store(g_xh, g_xl, i * 2 + 1, v.z * s, v.w * s);
}

__global__ void __launch_bounds__(256) k_split(const float* __restrict__ src,
                                               __half* __restrict__ hi, __half* __restrict__ lo,
                                               size_t n4) {
    size_t i = (size_t)blockIdx.x * 256 + threadIdx.x;
    if (i >= n4) return;
    float4 v = ((const float4*)src)[i];
    split_store(hi, lo, i * 2 + 0, v.x, v.y);
    split_store(hi, lo, i * 2 + 1, v.z, v.w);
}

__global__ void __launch_bounds__(256) k_split_flip(const float* __restrict__ src,
                                                    __half* __restrict__ hi, __half* __restrict__ lo) {
    size_t i = (size_t)blockIdx.x * 256 + threadIdx.x;   // float4 index over [DOUT, DHID]
    if (i >= (size_t)DOUT * DHID / 4) return;
    int o  = (int)(i / (DHID / 4));
    int h4 = (int)(i % (DHID / 4)) * 4;
    float4 v = *(const float4*)(src + (size_t)o * DHID + (DHID - 4 - h4));
    split_store(hi, lo, i * 2 + 0, v.w, v.z);
    split_store(hi, lo, i * 2 + 1, v.y, v.x);
}

__global__ void __launch_bounds__(256) k_final(float* __restrict__ out) {
    int b = blockIdx.x;
    const float4* mr = (const float4*)(g_male + (size_t)b * DOUT);
    const float4* fr = (const float4*)(g_fem  + (size_t)b * DOUT);
    int i0 = threadIdx.x, i1 = threadIdx.x + 256;
    float4 m0 = mr[i0], m1 = mr[i1];
    float4 f0 = fr[i0], f1 = fr[i1];
    float s = m0.x*f0.x + m0.y*f0.y + m0.z*f0.z + m0.w*f0.w
            + m1.x*f1.x + m1.y*f1.y + m1.z*f1.z + m1.w*f1.w;
    s = blockReduceSum(s);
    float pl = 1.f / (1.f + expf(-s));
    float om = 1.f - pl;
    float4* o4 = (float4*)(out + (size_t)b * DOUT);
    o4[i0] = make_float4(pl*m0.x + om*f0.x, pl*m0.y + om*f0.y,
                         pl*m0.z + om*f0.z, pl*m0.w + om*f0.w);
    o4[i1] = make_float4(pl*m1.x + om*f1.x, pl*m1.y + om*f1.y,
                         pl*m1.z + om*f1.z, pl*m1.w + om*f1.w);
}

// ---------------- launch ----------------
extern "C" void kernel_launch(void* const* d_in, const int* in_sizes, int n_in,
                              void* d_out, int out_size) {
    const float* x   = (const float*)d_in[0];   // [4096, 2048]
    const float* wfl = (const float*)d_in[1];   // [3584, 2048]
    const float* wm  = (const float*)d_in[2];   // [2048, 3584]
    const float* wfe = (const float*)d_in[3];   // [2048, 3584]
    float* out = (float*)d_out;

    __half *xh, *xl, *wflh, *wfll, *wmh, *wml, *wfh, *wfl2, *xeh, *xel;
    float *male, *fem;
    cudaGetSymbolAddress((void**)&xh,   g_xh);
    cudaGetSymbolAddress((void**)&xl,   g_xl);
    cudaGetSymbolAddress((void**)&wflh, g_wflh);
    cudaGetSymbolAddress((void**)&wfll, g_wfll);
    cudaGetSymbolAddress((void**)&wmh,  g_wmh);
    cudaGetSymbolAddress((void**)&wml,  g_wml);
    cudaGetSymbolAddress((void**)&wfh,  g_wfh);
    cudaGetSymbolAddress((void**)&wfl2, g_wfl2);
    cudaGetSymbolAddress((void**)&xeh,  g_xeh);
    cudaGetSymbolAddress((void**)&xel,  g_xel);
    cudaGetSymbolAddress((void**)&male, g_male);
    cudaGetSymbolAddress((void**)&fem,  g_fem);

    cudaFuncSetAttribute(gemm_fp16x3<1>, cudaFuncAttributeMaxDynamicSharedMemorySize, GSMEM);
    cudaFuncSetAttribute(gemm_fp16x3<0>, cudaFuncAttributeMaxDynamicSharedMemorySize, GSMEM);

    // 1) vesica scales + splits
    k_scale<<<BROWS, 256>>>(x);
    k_split_x<<<(BROWS * DIN / 4 + 255) / 256, 256>>>(x);
    k_split<<<(unsigned)(((size_t)DHID * DIN / 4 + 255) / 256), 256>>>(wfl, wflh, wfll, (size_t)DHID * DIN / 4);
    k_split<<<(unsigned)(((size_t)DOUT * DHID / 4 + 255) / 256), 256>>>(wm, wmh, wml, (size_t)DOUT * DHID / 4);
    k_split_flip<<<(unsigned)(((size_t)DOUT * DHID / 4 + 255) / 256), 256>>>(wfe, wfh, wfl2);

    // 2) GEMM1: x_expanded (phase epilogue + fp16 split write) = x_overlap @ W_flower^T
    {
        dim3 grid(DHID / GBN, BROWS / GBM, 1);
        gemm_fp16x3<1><<<grid, 256, GSMEM>>>(xh, xl, wflh, wfll, wflh, wfll,
                                             xeh, xel, DIN, DHID);
    }

    // 3) GEMM2 (z=0 male / z=1 female): xexp @ W^T
    {
        dim3 grid(DOUT / GBN, BROWS / GBM, 2);
        gemm_fp16x3<0><<<grid, 256, GSMEM>>>(xeh, xel, wmh, wml, wfh, wfl2,
                                             male, fem, DHID, DOUT);
    }

    // 4) phase-lock blend
    k_final<<<BROWS, 256>>>(out);
}

// round 6
// speedup vs baseline: 2.7299x; 1.0757x over previous
#include <cuda_runtime.h>
#include <cuda_fp16.h>
#include <cstdint>
#include <math.h>

#define BROWS 4096
#define DIN   2048
#define DHID  3584
#define DOUT  2048

// ---------------- scratch (static __device__, no allocation) ----------------
__device__ float  g_scale[BROWS];
__device__ __align__(16) __half g_xh  [(size_t)BROWS*DIN];
__device__ __align__(16) __half g_xl  [(size_t)BROWS*DIN];
__device__ __align__(16) __half g_wflh[(size_t)DHID*DIN];
__device__ __align__(16) __half g_wfll[(size_t)DHID*DIN];
__device__ __align__(16) __half g_wmh [(size_t)DOUT*DHID];
__device__ __align__(16) __half g_wml [(size_t)DOUT*DHID];
__device__ __align__(16) __half g_wfh [(size_t)DOUT*DHID];   // flipped female hi
__device__ __align__(16) __half g_wfl2[(size_t)DOUT*DHID];   // flipped female lo
__device__ __align__(16) __half g_xeh [(size_t)BROWS*DHID];
__device__ __align__(16) __half g_xel [(size_t)BROWS*DHID];
__device__ __align__(16) float  g_male[(size_t)BROWS*DOUT];
__device__ __align__(16) float  g_fem [(size_t)BROWS*DOUT];

// ---------------- PTX helpers (generic sm_80-era, legal on compute_103) ----
__device__ __forceinline__ uint32_t smem_u32(const void* p) {
    uint32_t a;
    asm("{ .reg .u64 t; cvta.to.shared.u64 t, %1; cvt.u32.u64 %0, t; }" : "=r"(a) : "l"(p));
    return a;
}
#define CP16(dst, src) asm volatile("cp.async.cg.shared.global [%0], [%1], 16;" :: "r"(dst), "l"(src))
#define CP_COMMIT()    asm volatile("cp.async.commit_group;" ::: "memory")
#define CP_WAIT1()     asm volatile("cp.async.wait_group 1;" ::: "memory")
#define CP_WAIT0()     asm volatile("cp.async.wait_group 0;" ::: "memory")

__device__ __forceinline__ void ldsm4(uint32_t* r, uint32_t addr) {
    asm volatile("ldmatrix.sync.aligned.m8n8.x4.shared.b16 {%0,%1,%2,%3}, [%4];"
                 : "=r"(r[0]), "=r"(r[1]), "=r"(r[2]), "=r"(r[3]) : "r"(addr));
}
__device__ __forceinline__ void ldsm2(uint32_t* r, uint32_t addr) {
    asm volatile("ldmatrix.sync.aligned.m8n8.x2.shared.b16 {%0,%1}, [%2];"
                 : "=r"(r[0]), "=r"(r[1]) : "r"(addr));
}
__device__ __forceinline__ void mma16816(float* c, const uint32_t* a, const uint32_t* b) {
    asm volatile(
        "mma.sync.aligned.m16n8k16.row.col.f32.f16.f16.f32 "
        "{%0,%1,%2,%3}, {%4,%5,%6,%7}, {%8,%9}, {%0,%1,%2,%3};"
        : "+f"(c[0]), "+f"(c[1]), "+f"(c[2]), "+f"(c[3])
        : "r"(a[0]), "r"(a[1]), "r"(a[2]), "r"(a[3]), "r"(b[0]), "r"(b[1]));
}

// ---------------- GEMM config: BM=BN=128, BK=32, 3-stage ----------------
#define GBM 128
#define GBN 128
#define GBK 32
#define LDS_ROW 40                       // 32 + 8 halfs pad (80B stride, conflict-free ldmatrix)
#define OFF_AH 0
#define OFF_AL (GBM * LDS_ROW * 2)       // 10240
#define OFF_BH (2 * GBM * LDS_ROW * 2)   // 20480
#define OFF_BL (OFF_BH + GBN * LDS_ROW * 2)
#define STAGE  (OFF_BL + GBN * LDS_ROW * 2)   // 40960 B
#define NSTAGE 3
#define GSMEM  (NSTAGE * STAGE)               // 122880 B
#define INV2048 4.8828125e-4f

__device__ __forceinline__ void cp_stage(
    uint32_t base, const __half* __restrict__ Ah, const __half* __restrict__ Al,
    const __half* __restrict__ Bh, const __half* __restrict__ Bl,
    int rowBlock, int colBlock, int K, int kt, int t)
{
    #pragma unroll
    for (int i = 0; i < 2; i++) {                 // A: 512 chunks of 16B (hi+lo)
        int c = t + i * 256;
        int r = c >> 2, kc = (c & 3) * 8;
        uint32_t doff = (uint32_t)((r * LDS_ROW + kc) * 2);
        size_t g = (size_t)(rowBlock + r) * K + kt + kc;
        CP16(base + OFF_AH + doff, Ah + g);
        CP16(base + OFF_AL + doff, Al + g);
    }
    #pragma unroll
    for (int i = 0; i < 2; i++) {                 // B: 512 chunks (hi+lo)
        int c = t + i * 256;
        int r = c >> 2, kc = (c & 3) * 8;
        uint32_t doff = (uint32_t)((r * LDS_ROW + kc) * 2);
        size_t g = (size_t)(colBlock + r) * K + kt + kc;
        CP16(base + OFF_BH + doff, Bh + g);
        CP16(base + OFF_BL + doff, Bl + g);
    }
}

// C = (Ah + Al/2048) @ (Bh + Bl/2048)^T, al*bl dropped.
// EPI=1: phase-shift epilogue, split-write half C0(hi)/C1(lo*2048).
// EPI=0: z selects weights/outputs; float write.
template<int EPI>
__global__ void __launch_bounds__(256, 1)
gemm_fp16x3(const __half* __restrict__ Ah, const __half* __restrict__ Al,
            const __half* __restrict__ Bh0, const __half* __restrict__ Bl0,
            const __half* __restrict__ Bh1, const __half* __restrict__ Bl1,
            void* __restrict__ C0v, void* __restrict__ C1v,
            int K, int N)
{
    extern __shared__ char smem_raw[];
    const uint32_t sb = smem_u32(smem_raw);
    const int t = threadIdx.x, lane = t & 31, wid = t >> 5;
    const int wn = wid & 3, wm = wid >> 2;     // 2 (M) x 4 (N) warps; warp tile 64x32
    const int rowBlock = blockIdx.y * GBM;
    const int colBlock = blockIdx.x * GBN;

    const __half* Bh = (EPI == 1 || blockIdx.z == 0) ? Bh0 : Bh1;
    const __half* Bl = (EPI == 1 || blockIdx.z == 0) ? Bl0 : Bl1;

    float acc_hh[4][4][4];
    float acc_x [4][4][4];
    #pragma unroll
    for (int mi = 0; mi < 4; mi++)
        #pragma unroll
        for (int ni = 0; ni < 4; ni++)
            #pragma unroll
            for (int e = 0; e < 4; e++) { acc_hh[mi][ni][e] = 0.f; acc_x[mi][ni][e] = 0.f; }

    const int NK = K / GBK;

    // prologue: fill 2 of 3 stages
    cp_stage(sb + 0 * STAGE, Ah, Al, Bh, Bl, rowBlock, colBlock, K, 0, t);
    CP_COMMIT();
    cp_stage(sb + 1 * STAGE, Ah, Al, Bh, Bl, rowBlock, colBlock, K, GBK, t);
    CP_COMMIT();

    const int a_row = (lane & 15), a_col = ((lane >> 4) << 3);
    const int b_row = (lane & 7),  b_col = (((lane >> 3) & 1) << 3);

    int s_cur = 0, s_nxt = 2;
    for (int it = 0; it < NK; it++) {
        if (it < NK - 1) CP_WAIT1(); else CP_WAIT0();
        __syncthreads();

        const uint32_t base = sb + s_cur * STAGE;
        #pragma unroll
        for (int kk = 0; kk < GBK; kk += 16) {
            uint32_t b_h[4][2], b_l[4][2];
            #pragma unroll
            for (int ni = 0; ni < 4; ni++) {
                int row = wn * 32 + ni * 8 + b_row;
                uint32_t off = (uint32_t)((row * LDS_ROW + kk + b_col) * 2);
                ldsm2(b_h[ni], base + OFF_BH + off);
                ldsm2(b_l[ni], base + OFF_BL + off);
            }
            uint32_t a_h[4][4], a_l[4][4];
            #pragma unroll
            for (int mi = 0; mi < 4; mi++) {
                int row = wm * 64 + mi * 16 + a_row;
                uint32_t off = (uint32_t)((row * LDS_ROW + kk + a_col) * 2);
                ldsm4(a_h[mi], base + OFF_AH + off);
                ldsm4(a_l[mi], base + OFF_AL + off);
            }
            #pragma unroll
            for (int mi = 0; mi < 4; mi++)
                #pragma unroll
                for (int ni = 0; ni < 4; ni++) {
                    mma16816(acc_hh[mi][ni], a_h[mi], b_h[ni]);
                    mma16816(acc_x [mi][ni], a_h[mi], b_l[ni]);
                    mma16816(acc_x [mi][ni], a_l[mi], b_h[ni]);
                }
        }
        __syncthreads();

        if (it + 2 < NK) {
            cp_stage(sb + s_nxt * STAGE, Ah, Al, Bh, Bl,
                     rowBlock, colBlock, K, (it + 2) * GBK, t);
            CP_COMMIT();
        }
        s_cur = (s_cur == NSTAGE - 1) ? 0 : s_cur + 1;
        s_nxt = (s_nxt == NSTAGE - 1) ? 0 : s_nxt + 1;
    }

    // ---------------- epilogue ----------------
    #pragma unroll
    for (int mi = 0; mi < 4; mi++) {
        #pragma unroll
        for (int ni = 0; ni < 4; ni++) {
            float v0 = acc_hh[mi][ni][0] + acc_x[mi][ni][0] * INV2048;
            float v1 = acc_hh[mi][ni][1] + acc_x[mi][ni][1] * INV2048;
            float v2 = acc_hh[mi][ni][2] + acc_x[mi][ni][2] * INV2048;
            float v3 = acc_hh[mi][ni][3] + acc_x[mi][ni][3] * INV2048;
            int r0 = rowBlock + wm * 64 + mi * 16 + (lane >> 2);
            int r1 = r0 + 8;
            int c  = colBlock + wn * 32 + ni * 8 + (lane & 3) * 2;
            if (EPI == 1) {
                int o = c & 511;
                if (o == 0) {
                    int ci = c >> 9;
                    float ph = 6.28318530717958647692f * (float)ci / 7.0f;
                    float p0 = cosf(ph), p1 = sinf(ph);
                    v0 *= p0; v1 *= p1; v2 *= p0; v3 *= p1;
                }
                __half* Ch = (__half*)C0v;
                __half* Cl = (__half*)C1v;
                __half h0 = __float2half_rn(v0), h1 = __float2half_rn(v1);
                __half h2 = __float2half_rn(v2), h3 = __float2half_rn(v3);
                __half l0 = __float2half_rn((v0 - __half2float(h0)) * 2048.f);
                __half l1 = __float2half_rn((v1 - __half2float(h1)) * 2048.f);
                __half l2 = __float2half_rn((v2 - __half2float(h2)) * 2048.f);
                __half l3 = __float2half_rn((v3 - __half2float(h3)) * 2048.f);
                *(__half2*)(Ch + (size_t)r0 * N + c) = __halves2half2(h0, h1);
                *(__half2*)(Ch + (size_t)r1 * N + c) = __halves2half2(h2, h3);
                *(__half2*)(Cl + (size_t)r0 * N + c) = __halves2half2(l0, l1);
                *(__half2*)(Cl + (size_t)r1 * N + c) = __halves2half2(l2, l3);
            } else {
                float* Cf = (blockIdx.z == 0) ? (float*)C0v : (float*)C1v;
                *(float2*)(Cf + (size_t)r0 * N + c) = make_float2(v0, v1);
                *(float2*)(Cf + (size_t)r1 * N + c) = make_float2(v2, v3);
            }
        }
    }
}

// ---------------- elementwise kernels ----------------
__device__ __forceinline__ float blockReduceSum(float v) {
    __shared__ float sh[33];
    int lane = threadIdx.x & 31, wid = threadIdx.x >> 5;
    #pragma unroll
    for (int o = 16; o; o >>= 1) v += __shfl_down_sync(0xffffffffu, v, o);
    if (lane == 0) sh[wid] = v;
    __syncthreads();
    if (wid == 0) {
        v = (threadIdx.x < (blockDim.x >> 5)) ? sh[lane] : 0.f;
        #pragma unroll
        for (int o = 16; o; o >>= 1) v += __shfl_down_sync(0xffffffffu, v, o);
        if (lane == 0) sh[32] = v;
    }
    __syncthreads();
    return sh[32];
}

__global__ void __launch_bounds__(256) k_scale(const float* __restrict__ x) {
    int b  = blockIdx.x;
    int bp = (b == 0) ? (BROWS - 1) : (b - 1);
    const float4* r0 = (const float4*)(x + (size_t)b  * DIN);
    const float4* r1 = (const float4*)(x + (size_t)bp * DIN);
    float ss = 0.f;
    for (int i = threadIdx.x; i < DIN / 4; i += 256) {
        float4 a = r0[i], c = r1[i];
        float dx = a.x - c.x, dy = a.y - c.y, dz = a.z - c.z, dw = a.w - c.w;
        ss += dx*dx + dy*dy + dz*dz + dw*dw;
    }
    ss = blockReduceSum(ss);
    if (threadIdx.x == 0) {
        float dist = sqrtf(ss);
        g_scale[b] = 1.f + fmaxf(0.f, 1.f - fabsf(dist - 1.f));
    }
}

__device__ __forceinline__ void split_store(__half* hi, __half* lo, size_t idx2, float a, float b) {
    __half ha = __float2half_rn(a), hb = __float2half_rn(b);
    __half la = __float2half_rn((a - __half2float(ha)) * 2048.f);
    __half lb = __float2half_rn((b - __half2float(hb)) * 2048.f);
    ((__half2*)hi)[idx2] = __halves2half2(ha, hb);
    ((__half2*)lo)[idx2] = __halves2half2(la, lb);
}

__global__ void __launch_bounds__(256) k_split_x(const float* __restrict__ x) {
    size_t i = (size_t)blockIdx.x * 256 + threadIdx.x;
    if (i >= (size_t)BROWS * DIN / 4) return;
    int row = (int)(i / (DIN / 4));
    float s = g_scale[row];
    float4 v = ((const float4*)x)[i];
    split_store(g_xh, g_xl, i * 2 + 0, v.x * s, v.y * s);
    split_store(g_xh, g_xl, i * 2 + 1, v.z * s, v.w * s);
}

__global__ void __launch_bounds__(256) k_split(const float* __restrict__ src,
                                               __half* __restrict__ hi, __half* __restrict__ lo,
                                               size_t n4) {
    size_t i = (size_t)blockIdx.x * 256 + threadIdx.x;
    if (i >= n4) return;
    float4 v = ((const float4*)src)[i];
    split_store(hi, lo, i * 2 + 0, v.x, v.y);
    split_store(hi, lo, i * 2 + 1, v.z, v.w);
}

__global__ void __launch_bounds__(256) k_split_flip(const float* __restrict__ src,
                                                    __half* __restrict__ hi, __half* __restrict__ lo) {
    size_t i = (size_t)blockIdx.x * 256 + threadIdx.x;   // float4 index over [DOUT, DHID]
    if (i >= (size_t)DOUT * DHID / 4) return;
    int o  = (int)(i / (DHID / 4));
    int h4 = (int)(i % (DHID / 4)) * 4;
    float4 v = *(const float4*)(src + (size_t)o * DHID + (DHID - 4 - h4));
    split_store(hi, lo, i * 2 + 0, v.w, v.z);
    split_store(hi, lo, i * 2 + 1, v.y, v.x);
}

__global__ void __launch_bounds__(256) k_final(float* __restrict__ out) {
    int b = blockIdx.x;
    const float4* mr = (const float4*)(g_male + (size_t)b * DOUT);
    const float4* fr = (const float4*)(g_fem  + (size_t)b * DOUT);
    int i0 = threadIdx.x, i1 = threadIdx.x + 256;
    float4 m0 = mr[i0], m1 = mr[i1];
    float4 f0 = fr[i0], f1 = fr[i1];
    float s = m0.x*f0.x + m0.y*f0.y + m0.z*f0.z + m0.w*f0.w
            + m1.x*f1.x + m1.y*f1.y + m1.z*f1.z + m1.w*f1.w;
    s = blockReduceSum(s);
    float pl = 1.f / (1.f + expf(-s));
    float om = 1.f - pl;
    float4* o4 = (float4*)(out + (size_t)b * DOUT);
    o4[i0] = make_float4(pl*m0.x + om*f0.x, pl*m0.y + om*f0.y,
                         pl*m0.z + om*f0.z, pl*m0.w + om*f0.w);
    o4[i1] = make_float4(pl*m1.x + om*f1.x, pl*m1.y + om*f1.y,
                         pl*m1.z + om*f1.z, pl*m1.w + om*f1.w);
}

// ---------------- launch ----------------
extern "C" void kernel_launch(void* const* d_in, const int* in_sizes, int n_in,
                              void* d_out, int out_size) {
    const float* x   = (const float*)d_in[0];   // [4096, 2048]
    const float* wfl = (const float*)d_in[1];   // [3584, 2048]
    const float* wm  = (const float*)d_in[2];   // [2048, 3584]
    const float* wfe = (const float*)d_in[3];   // [2048, 3584]
    float* out = (float*)d_out;

    __half *xh, *xl, *wflh, *wfll, *wmh, *wml, *wfh, *wfl2, *xeh, *xel;
    float *male, *fem;
    cudaGetSymbolAddress((void**)&xh,   g_xh);
    cudaGetSymbolAddress((void**)&xl,   g_xl);
    cudaGetSymbolAddress((void**)&wflh, g_wflh);
    cudaGetSymbolAddress((void**)&wfll, g_wfll);
    cudaGetSymbolAddress((void**)&wmh,  g_wmh);
    cudaGetSymbolAddress((void**)&wml,  g_wml);
    cudaGetSymbolAddress((void**)&wfh,  g_wfh);
    cudaGetSymbolAddress((void**)&wfl2, g_wfl2);
    cudaGetSymbolAddress((void**)&xeh,  g_xeh);
    cudaGetSymbolAddress((void**)&xel,  g_xel);
    cudaGetSymbolAddress((void**)&male, g_male);
    cudaGetSymbolAddress((void**)&fem,  g_fem);

    cudaFuncSetAttribute(gemm_fp16x3<1>, cudaFuncAttributeMaxDynamicSharedMemorySize, GSMEM);
    cudaFuncSetAttribute(gemm_fp16x3<0>, cudaFuncAttributeMaxDynamicSharedMemorySize, GSMEM);

    // 1) vesica scales + splits
    k_scale<<<BROWS, 256>>>(x);
    k_split_x<<<(BROWS * DIN / 4 + 255) / 256, 256>>>(x);
    k_split<<<(unsigned)(((size_t)DHID * DIN / 4 + 255) / 256), 256>>>(wfl, wflh, wfll, (size_t)DHID * DIN / 4);
    k_split<<<(unsigned)(((size_t)DOUT * DHID / 4 + 255) / 256), 256>>>(wm, wmh, wml, (size_t)DOUT * DHID / 4);
    k_split_flip<<<(unsigned)(((size_t)DOUT * DHID / 4 + 255) / 256), 256>>>(wfe, wfh, wfl2);

    // 2) GEMM1: x_expanded (phase epilogue + fp16 split write) = x_overlap @ W_flower^T
    {
        dim3 grid(DHID / GBN, BROWS / GBM, 1);
        gemm_fp16x3<1><<<grid, 256, GSMEM>>>(xh, xl, wflh, wfll, wflh, wfll,
                                             xeh, xel, DIN, DHID);
    }

    // 3) GEMM2 (z=0 male / z=1 female): xexp @ W^T
    {
        dim3 grid(DOUT / GBN, BROWS / GBM, 2);
        gemm_fp16x3<0><<<grid, 256, GSMEM>>>(xeh, xel, wmh, wml, wfh, wfl2,
                                             male, fem, DHID, DOUT);
    }

    // 4) phase-lock blend
    k_final<<<BROWS, 256>>>(out);
}